// round 2
// baseline (speedup 1.0000x reference)
#include <cuda_runtime.h>
#include <cuda_bf16.h>

// Problem constants
#define NQ 15          // qubits
#define NB 512         // batch
#define BPB 8          // batches per block in expect kernel

// O_k matrices: 15 real symmetric 32x32 (5-qubit light-cone operators)
__device__ float g_O[NQ][32][32];

// ---------------------------------------------------------------------------
// Kernel 1: build O_k = B_w^T * Z_center * B_w for each k, where
// B_w = R3 * Z2 * R2 * Z1 restricted to the 5-qubit window [k-2, k+2].
// Grid: 15 blocks x 32 threads. Thread j owns column j of the 32x32 matrix.
// ---------------------------------------------------------------------------
__global__ void build_O(const float* __restrict__ theta) {
    const int k = blockIdx.x;
    const int j = threadIdx.x;

    __shared__ float M[32][32];   // M[row][col]

    // CZ-layer sign for a 5-bit window index (pairs (s,s+1) <-> qubits (k-2+s, k-1+s))
    auto czsign = [&](int idx) -> float {
        float z = 1.0f;
        #pragma unroll
        for (int s = 0; s < 4; s++) {
            int q = k - 2 + s;
            if (q >= 0 && q + 1 <= NQ - 1) {
                if (((idx >> s) & 1) && ((idx >> (s + 1)) & 1)) z = -z;
            }
        }
        return z;
    };

    // M = Z1 (diagonal) * I
    #pragma unroll
    for (int i = 0; i < 32; i++) M[i][j] = 0.0f;
    M[j][j] = czsign(j);

    // M <- R2 * M  (RY(theta[15+q]) on each valid window slot; column-local)
    #pragma unroll
    for (int s = 0; s < 5; s++) {
        int q = k - 2 + s;
        if (q < 0 || q > NQ - 1) continue;
        float c, sn;
        sincosf(0.5f * theta[15 + q], &sn, &c);
        int bit = 1 << s;
        for (int i0 = 0; i0 < 32; i0++) {
            if (i0 & bit) continue;
            int i1 = i0 | bit;
            float a = M[i0][j], b = M[i1][j];
            M[i0][j] = c * a - sn * b;
            M[i1][j] = sn * a + c * b;
        }
    }

    // M <- Z2 * M (row scaling)
    for (int i = 0; i < 32; i++) M[i][j] *= czsign(i);

    // M <- R3 * M  (RY(theta[30+q]))
    #pragma unroll
    for (int s = 0; s < 5; s++) {
        int q = k - 2 + s;
        if (q < 0 || q > NQ - 1) continue;
        float c, sn;
        sincosf(0.5f * theta[30 + q], &sn, &c);
        int bit = 1 << s;
        for (int i0 = 0; i0 < 32; i0++) {
            if (i0 & bit) continue;
            int i1 = i0 | bit;
            float a = M[i0][j], b = M[i1][j];
            M[i0][j] = c * a - sn * b;
            M[i1][j] = sn * a + c * b;
        }
    }

    __syncwarp();

    // colj[l] = zc(l) * M[l][j]  (zc = Z on center slot = bit 2)
    float colj[32];
    #pragma unroll
    for (int l = 0; l < 32; l++) {
        float zc = ((l >> 2) & 1) ? -1.0f : 1.0f;
        colj[l] = zc * M[l][j];
    }

    // O[i][j] = sum_l M[l][i] * colj[l]   (broadcast reads of M[l][i])
    for (int i = 0; i < 32; i++) {
        float acc = 0.0f;
        #pragma unroll
        for (int l = 0; l < 32; l++) acc += M[l][i] * colj[l];
        g_O[k][i][j] = acc;
    }
}

// ---------------------------------------------------------------------------
// Kernel 2: per batch b, e_k = w^T O_k w (real part decomposition), then
// out[b] = head_b + sum_k head_w[14-k] * e_k.
// Block: 480 threads = 15 warps; warp k handles operator O_k for 8 batches.
// Grid: 64 blocks (512 batches).
// ---------------------------------------------------------------------------
__global__ void __launch_bounds__(480) expect_kernel(
    const float* __restrict__ sb,      // state_batch [512][15]
    const float* __restrict__ theta,   // [45]
    const float* __restrict__ hw,      // head_w [15]
    const float* __restrict__ hb,      // head_b [1]
    float* __restrict__ out)           // [512]
{
    __shared__ float  sv[BPB][NQ][4];     // per-batch single-qubit factors v_q
    __shared__ float2 swbuf[NQ][32];      // per-warp 32-dim product vector w
    __shared__ float  eSm[BPB][NQ];       // e_k values

    const int tid = threadIdx.x;
    const int b0  = blockIdx.x * BPB;

    // Compute v_q = RY(theta[q]) RX(x_{b,q}) |0> for each (local batch, qubit).
    // v0 = ct*ca + i*st*sa ; v1 = st*ca - i*ct*sa
    if (tid < BPB * NQ) {
        int bl = tid / NQ, q = tid - bl * NQ;
        float ca, sa, ct, st;
        sincosf(0.5f * sb[(b0 + bl) * NQ + q], &sa, &ca);
        sincosf(0.5f * theta[q], &st, &ct);
        sv[bl][q][0] = ct * ca;
        sv[bl][q][1] = st * sa;
        sv[bl][q][2] = st * ca;
        sv[bl][q][3] = -ct * sa;
    }
    __syncthreads();

    const int k    = tid >> 5;    // warp id == operator index (0..14)
    const int lane = tid & 31;

    // Register-resident O column: o[j] = O_k[j][lane] = O_k[lane][j] (symmetric)
    float o[32];
    #pragma unroll
    for (int j = 0; j < 32; j++) o[j] = g_O[k][j][lane];

    for (int bl = 0; bl < BPB; bl++) {
        // Build w_lane = prod over 5 window slots of factor component per bit.
        float wr = 1.0f, wi = 0.0f;
        #pragma unroll
        for (int s = 0; s < 5; s++) {
            int q = k - 2 + s;
            int bit = (lane >> s) & 1;
            float fr, fi;
            if (q >= 0 && q <= NQ - 1) {
                fr = sv[bl][q][bit * 2];
                fi = sv[bl][q][bit * 2 + 1];
            } else {
                fr = bit ? 0.0f : 1.0f;   // virtual qubit fixed to |0>
                fi = 0.0f;
            }
            float nr = wr * fr - wi * fi;
            wi = wr * fi + wi * fr;
            wr = nr;
        }

        swbuf[k][lane] = make_float2(wr, wi);
        __syncwarp();

        // (O w)_lane for real and imag parts via smem broadcast
        float ar = 0.0f, ai = 0.0f;
        #pragma unroll
        for (int j = 0; j < 32; j++) {
            float2 wj = swbuf[k][j];
            ar += o[j] * wj.x;
            ai += o[j] * wj.y;
        }

        float e = wr * ar + wi * ai;
        #pragma unroll
        for (int off = 16; off; off >>= 1)
            e += __shfl_xor_sync(0xffffffffu, e, off);

        if (lane == 0) eSm[bl][k] = e;
        __syncwarp();   // protect swbuf before next iteration's overwrite
    }

    __syncthreads();

    // Head: out[b] = hb + sum_k hw[14-k] * e_k
    if (tid < BPB) {
        float acc = hb[0];
        #pragma unroll
        for (int kk = 0; kk < NQ; kk++) acc += hw[(NQ - 1) - kk] * eSm[tid][kk];
        out[b0 + tid] = acc;
    }
}

// ---------------------------------------------------------------------------
extern "C" void kernel_launch(void* const* d_in, const int* in_sizes, int n_in,
                              void* d_out, int out_size) {
    const float* sb    = (const float*)d_in[0];  // state_batch [512*15]
    const float* theta = (const float*)d_in[1];  // [45]
    const float* hw    = (const float*)d_in[2];  // head_w [15]
    const float* hb    = (const float*)d_in[3];  // head_b [1]
    float* out = (float*)d_out;                  // [512]

    build_O<<<NQ, 32>>>(theta);
    expect_kernel<<<NB / BPB, 480>>>(sb, theta, hw, hb, out);
}

// round 3
// speedup vs baseline: 1.9412x; 1.9412x over previous
#include <cuda_runtime.h>
#include <cuda_bf16.h>

#define NQ 15
#define NB 512
#define FULLM 0xffffffffu

// ---------------------------------------------------------------------------
// One fused kernel. CTA b handles batch b with 15 warps; warp k computes
// e_k = <psi_b| O_k |psi_b> by directly evolving the 5-qubit (32-dim) window
// state in registers (one complex amplitude per lane):
//   w = prod_q RY(theta_q) RX(x_bq)|0>   (product state, window-restricted)
//   state = R3 * Z2 * R2 * Z1 * w        (CZ signs lane-local, RY via shfl)
//   e_k = sum_lane sign(bit2) * |state|^2
// Final CZ layer is diagonal => dropped (probabilities unchanged).
// Light-cone: O_k supported on qubits [k-2, k+2]; gates outside the window
// commute through and cancel, so window restriction is exact.
// ---------------------------------------------------------------------------
__global__ void __launch_bounds__(480, 4) fused_expect(
    const float* __restrict__ sb,      // state_batch [512][15]
    const float* __restrict__ theta,   // [45]
    const float* __restrict__ hw,      // head_w [15]
    const float* __restrict__ hb,      // head_b [1]
    float* __restrict__ out)           // [512]
{
    __shared__ float sfac[NQ][5][8];   // per (warp, slot): v0r v0i v1r v1i c2 s2 c3 s3
    __shared__ float eSm[NQ];

    const int tid  = threadIdx.x;
    const int k    = tid >> 5;         // warp id == operator index 0..14
    const int lane = tid & 31;
    const int b    = blockIdx.x;

    // Lanes 0..4 compute the single-qubit factors + gate angles for slot s.
    if (lane < 5) {
        int q = k - 2 + lane;
        float v0r = 1.f, v0i = 0.f, v1r = 0.f, v1i = 0.f;
        float c2 = 1.f, s2 = 0.f, c3 = 1.f, s3 = 0.f;
        if (q >= 0 && q < NQ) {
            float ca, sa, ct, st;
            sincosf(0.5f * sb[b * NQ + q], &sa, &ca);   // RX(x) data angle
            sincosf(0.5f * theta[q],       &st, &ct);   // RY layer 1
            // v = RY(theta1) RX(x) |0>
            v0r = ct * ca;  v0i = st * sa;
            v1r = st * ca;  v1i = -ct * sa;
            sincosf(0.5f * theta[NQ + q],     &s2, &c2); // RY layer 2
            sincosf(0.5f * theta[2 * NQ + q], &s3, &c3); // RY layer 3
        }
        float* p = sfac[k][lane];
        p[0] = v0r; p[1] = v0i; p[2] = v1r; p[3] = v1i;
        p[4] = c2;  p[5] = s2;  p[6] = c3;  p[7] = s3;
    }
    __syncwarp();

    // Build product-state amplitude for this lane's 5-bit index.
    float r = 1.f, m = 0.f;
    #pragma unroll
    for (int s = 0; s < 5; s++) {
        const float* p = sfac[k][s] + ((lane >> s) & 1) * 2;
        float fr = p[0], fi = p[1];
        float nr = r * fr - m * fi;
        m = r * fi + m * fr;
        r = nr;
    }

    // CZ pair-validity mask for this window (pair s <-> qubits k-2+s, k-1+s).
    int smin = 2 - k;  if (smin < 0) smin = 0;
    int smax = 15 - k; if (smax > 3) smax = 3;
    unsigned pmask = 0;
    #pragma unroll
    for (int s = 0; s < 4; s++)
        if (s >= smin && s <= smax) pmask |= 1u << s;

    // CZ layer 1 (lane-local diagonal signs)
    if (__popc(lane & (lane >> 1) & pmask) & 1) { r = -r; m = -m; }

    // RY layer 2: butterfly per valid slot (warp-uniform branch)
    #pragma unroll
    for (int s = 0; s < 5; s++) {
        int q = k - 2 + s;
        if (q < 0 || q >= NQ) continue;
        float c  = sfac[k][s][4], sn = sfac[k][s][5];
        float pr = __shfl_xor_sync(FULLM, r, 1 << s);
        float pm = __shfl_xor_sync(FULLM, m, 1 << s);
        float sg = ((lane >> s) & 1) ? sn : -sn;
        r = fmaf(sg, pr, c * r);
        m = fmaf(sg, pm, c * m);
    }

    // CZ layer 2
    if (__popc(lane & (lane >> 1) & pmask) & 1) { r = -r; m = -m; }

    // RY layer 3
    #pragma unroll
    for (int s = 0; s < 5; s++) {
        int q = k - 2 + s;
        if (q < 0 || q >= NQ) continue;
        float c  = sfac[k][s][6], sn = sfac[k][s][7];
        float pr = __shfl_xor_sync(FULLM, r, 1 << s);
        float pm = __shfl_xor_sync(FULLM, m, 1 << s);
        float sg = ((lane >> s) & 1) ? sn : -sn;
        r = fmaf(sg, pr, c * r);
        m = fmaf(sg, pm, c * m);
    }

    // <Z_center>: center qubit is window bit 2.
    float p = fmaf(r, r, m * m);
    float e = ((lane >> 2) & 1) ? -p : p;
    #pragma unroll
    for (int off = 16; off; off >>= 1)
        e += __shfl_xor_sync(FULLM, e, off);

    if (lane == 0) eSm[k] = e;
    __syncthreads();

    // Head: out[b] = hb + sum_k hw[14-k] * e_k
    if (tid == 0) {
        float acc = hb[0];
        #pragma unroll
        for (int kk = 0; kk < NQ; kk++)
            acc = fmaf(hw[(NQ - 1) - kk], eSm[kk], acc);
        out[b] = acc;
    }
}

// ---------------------------------------------------------------------------
extern "C" void kernel_launch(void* const* d_in, const int* in_sizes, int n_in,
                              void* d_out, int out_size) {
    const float* sb    = (const float*)d_in[0];
    const float* theta = (const float*)d_in[1];
    const float* hw    = (const float*)d_in[2];
    const float* hb    = (const float*)d_in[3];
    float* out = (float*)d_out;

    fused_expect<<<NB, NQ * 32>>>(sb, theta, hw, hb, out);
}

// round 4
// speedup vs baseline: 2.5882x; 1.3333x over previous
#include <cuda_runtime.h>
#include <cuda_bf16.h>

#define NQ 15
#define NB 512
#define FULLM 0xffffffffu

// ---------------------------------------------------------------------------
// Closed-form Pauli expansion of O_k = circuit^dagger Z_k circuit:
//   e_k = c3*( c2c*zc - s2c*zb*xc*zd )
//       - s3*(  c2b*c2c*c2d*xc
//             - c2b*c2c*s2d*yc*yd*ze
//             + c2b*s2c*c2d*zb*zc*zd
//             - c2b*s2c*s2d*zb*xd*ze
//             - s2b*c2c*c2d*za*yb*yc
//             - s2b*c2c*s2d*za*yb*xc*yd*ze
//             - s2b*s2c*c2d*za*xb*zd
//             + s2b*s2c*s2d*za*xb*zc*xd*ze )
// slots a..e = qubits k-2..k+2; angles are FULL angles.
// Per-qubit product-state expectations: z=cos(t1)cos(x), x=sin(t1)cos(x), y=-sin(x).
// Out-of-range qubits: z=1, x=y=0, c2=1, s2=0 (|0>, identity gates) - uniform.
// Warp = one batch, lane = k. 32 blocks x 512 threads = 512 warps.
// ---------------------------------------------------------------------------
__global__ void __launch_bounds__(512, 1) fused_pauli(
    const float* __restrict__ sb,      // [512][15]
    const float* __restrict__ theta,   // [45]
    const float* __restrict__ hw,      // [15]
    const float* __restrict__ hb,      // [1]
    float* __restrict__ out)           // [512]
{
    __shared__ float tg[NQ][6];        // c1,s1,c2,s2,c3,s3 (full angles)
    __shared__ float hwS[NQ];

    const int tid = threadIdx.x;
    if (tid < NQ) {
        float c1, s1, c2, s2, c3, s3;
        __sincosf(theta[tid],          &s1, &c1);
        __sincosf(theta[NQ + tid],     &s2, &c2);
        __sincosf(theta[2 * NQ + tid], &s3, &c3);
        tg[tid][0] = c1; tg[tid][1] = s1;
        tg[tid][2] = c2; tg[tid][3] = s2;
        tg[tid][4] = c3; tg[tid][5] = s3;
        hwS[tid] = hw[(NQ - 1) - tid];  // pre-reversed head weight
    }
    __syncthreads();

    const int wid  = tid >> 5;
    const int lane = tid & 31;
    const int b    = blockIdx.x * 16 + wid;

    // Lane q (<15) owns cos/sin of its data angle x_{b,q}.
    float cx = 0.f, sx = 0.f;
    if (lane < NQ) {
        float xv = sb[b * NQ + lane];
        __sincosf(xv, &sx, &cx);
    }

    // Gather the 5 window slots via shfl; compute expectations + layer-2 trig.
    float z[5], X[5], Y[5], C2[5], S2[5];
    #pragma unroll
    for (int s = 0; s < 5; s++) {
        int  q     = lane - 2 + s;
        bool valid = (q >= 0) && (q < NQ) && (lane < NQ);
        int  qc    = valid ? q : 0;
        float cg = __shfl_sync(FULLM, cx, qc);
        float sg = __shfl_sync(FULLM, sx, qc);
        z[s]  = valid ? tg[qc][0] * cg : 1.f;
        X[s]  = valid ? tg[qc][1] * cg : 0.f;
        Y[s]  = valid ? -sg            : 0.f;
        C2[s] = valid ? tg[qc][2]      : 1.f;
        S2[s] = valid ? tg[qc][3]      : 0.f;
    }

    const int lc = (lane < NQ) ? lane : 0;
    const float c3k = tg[lc][4], s3k = tg[lc][5];

    const float za = z[0], zb = z[1], zc = z[2], zd = z[3], ze = z[4];
    const float xb = X[1], xc = X[2], xd = X[3];
    const float yb = Y[1], yc = Y[2], yd = Y[3];
    const float c2b = C2[1], c2c = C2[2], c2d = C2[3];
    const float s2b = S2[1], s2c = S2[2], s2d = S2[3];

    float br =  c2b * c2c * c2d * xc
             -  c2b * c2c * s2d * (yc * yd * ze)
             +  c2b * s2c * c2d * (zb * zc * zd)
             -  c2b * s2c * s2d * (zb * xd * ze)
             -  s2b * c2c * c2d * (za * yb * yc)
             -  s2b * c2c * s2d * (za * yb * xc * yd * ze)
             -  s2b * s2c * c2d * (za * xb * zd)
             +  s2b * s2c * s2d * (za * xb * zc * xd * ze);

    float ek = c3k * (c2c * zc - s2c * (zb * xc * zd)) - s3k * br;

    // Weighted reduce across the 15 operator lanes.
    float e = (lane < NQ) ? hwS[lane] * ek : 0.f;
    #pragma unroll
    for (int off = 16; off; off >>= 1)
        e += __shfl_xor_sync(FULLM, e, off);

    if (lane == 0) out[b] = e + hb[0];
}

// ---------------------------------------------------------------------------
extern "C" void kernel_launch(void* const* d_in, const int* in_sizes, int n_in,
                              void* d_out, int out_size) {
    const float* sb    = (const float*)d_in[0];
    const float* theta = (const float*)d_in[1];
    const float* hw    = (const float*)d_in[2];
    const float* hb    = (const float*)d_in[3];
    float* out = (float*)d_out;

    fused_pauli<<<NB / 16, 512>>>(sb, theta, hw, hb, out);
}